// round 10
// baseline (speedup 1.0000x reference)
#include <cuda_runtime.h>
#include <math.h>

#define T_DIM   512
#define B_DIM   2048
#define IN_DIMC 64
#define OBS_MID 28
#define OBS_BN  8
#define NQ      6561   /* 3^8 */

#define MEMO_BKT_BITS 21
#define MEMO_BKTS     (1u << MEMO_BKT_BITS)   /* 2M buckets x 16B = 32MB */
#define MEMO_BKT_MASK (MEMO_BKTS - 1u)

// ---- persistent device scratch ----
__device__ float4 g_GHM[(NQ + 1) * 16];   // (gh_r, gh_z, gh_n, m) per state, per lane
__device__ float4 g_GI4[NQ * 16];         // (gi_r, gi_z, gi_n, 0) per obs code, per lane
__device__ float  g_OUT[NQ * 16];         // tanh(M[q] @ act_w^T + act_b)
__device__ float  g_thr;                  // ternary decision threshold
__device__ __align__(16) unsigned long long g_memo[MEMO_BKTS * 2]; // 2-way buckets

__device__ __forceinline__ float sigf(float x) {
    return 0.5f + 0.5f * tanhf(0.5f * x);
}

// f32x2 packed-FMA helpers
__device__ __forceinline__ unsigned long long pack2(float a, float b) {
    unsigned long long r;
    asm("mov.b64 %0, {%1, %2};" : "=l"(r) : "f"(a), "f"(b));
    return r;
}
__device__ __forceinline__ void unpack2(unsigned long long v, float& a, float& b) {
    asm("mov.b64 {%0, %1}, %2;" : "=f"(a), "=f"(b) : "l"(v));
}
__device__ __forceinline__ void ffma2(unsigned long long& d, unsigned long long a,
                                      unsigned long long b) {
    asm("fma.rn.f32x2 %0, %1, %2, %0;" : "+l"(d) : "l"(a), "l"(b));
}

// ---------------------------------------------------------------------------
__global__ void memo_clear() {
    reinterpret_cast<ulonglong2*>(g_memo)[blockIdx.x * blockDim.x + threadIdx.x] =
        make_ulonglong2(0ull, 0ull);
}

// ---------------------------------------------------------------------------
// Setup: 16-lane groups, one state code per group, shfl exchanges.
// ---------------------------------------------------------------------------
__global__ __launch_bounds__(256) void setup_all(
    const float* __restrict__ q2m_w0, const float* __restrict__ q2m_b0,
    const float* __restrict__ q2m_w1, const float* __restrict__ q2m_b1,
    const float* __restrict__ q2m_w2, const float* __restrict__ q2m_b2,
    const float* __restrict__ act_w,  const float* __restrict__ act_b,
    const float* __restrict__ wih, const float* __restrict__ whh,
    const float* __restrict__ bih, const float* __restrict__ bhh)
{
    const int tid = threadIdx.x;
    const int j   = tid & 15;
    int g = blockIdx.x * 16 + (tid >> 4);
    if (blockIdx.x == 0 && tid == 0) {
        float lo = 0.0f, hi = 2.0f;
        for (int it = 0; it < 80; it++) {
            float mid = 0.5f * (lo + hi);
            if (mid <= lo || mid >= hi) break;
            float s = 1.5f * tanhf(mid) + 0.5f * tanhf(-3.0f * mid);
            if (s > 0.5f) hi = mid; else lo = mid;
        }
        g_thr = lo;
    }
    bool real = (g < NQ);
    if (g > NQ) { g = NQ; real = false; }

    float q[8];
    if (real) {
        int r = g;
        #pragma unroll
        for (int i = 0; i < 8; i++) { q[i] = (float)(r % 3 - 1); r /= 3; }
    }

    float m2j = 0.0f;
    if (real) {
        float a = 0.0f;
        #pragma unroll
        for (int k = 0; k < 8; k++) a += q2m_w0[j * 8 + k] * q[k];
        float m0j = tanhf(a + q2m_b0[j]);

        float a1 = 0.0f;
        #pragma unroll
        for (int k = 0; k < 16; k++)
            a1 += q2m_w1[j * 16 + k] * __shfl_sync(0xffffffffu, m0j, k, 16);
        float m1j = tanhf(a1 + q2m_b1[j]);

        float a2 = 0.0f;
        #pragma unroll
        for (int k = 0; k < 16; k++)
            a2 += q2m_w2[j * 16 + k] * __shfl_sync(0xffffffffu, m1j, k, 16);
        m2j = tanhf(a2 + q2m_b2[j]);

        float ao = 0.0f;
        #pragma unroll
        for (int k = 0; k < 16; k++)
            ao += act_w[j * 16 + k] * __shfl_sync(0xffffffffu, m2j, k, 16);
        g_OUT[g * 16 + j] = tanhf(ao + act_b[j]);
    }

    {
        float ar = 0.0f, az = 0.0f, an = 0.0f;
        #pragma unroll
        for (int k = 0; k < 16; k++) {
            float mk = __shfl_sync(0xffffffffu, m2j, k, 16);
            ar += mk * whh[j * 16 + k];
            az += mk * whh[(16 + j) * 16 + k];
            an += mk * whh[(32 + j) * 16 + k];
        }
        g_GHM[g * 16 + j] = make_float4(ar + bhh[j], az + bhh[16 + j],
                                        an + bhh[32 + j], m2j);
    }
    if (real) {
        float ar = 0.0f, az = 0.0f, an = 0.0f;
        #pragma unroll
        for (int k = 0; k < 8; k++) {
            ar += q[k] * wih[j * 8 + k];
            az += q[k] * wih[(16 + j) * 8 + k];
            an += q[k] * wih[(32 + j) * 8 + k];
        }
        g_GI4[g * 16 + j] = make_float4(ar + bih[j], az + bih[16 + j],
                                        an + bih[32 + j], 0.0f);
    }
}

// ---------------------------------------------------------------------------
// Fused kernel: warps 0-3 = obs producer, warps 4-7 = recurrence with
// per-launch transition memoization. Hit decision is PER 16-LANE GROUP
// (independent batch columns), so one cold trajectory no longer drags its
// warp-mate through full compute.
// ---------------------------------------------------------------------------
__global__ __launch_bounds__(256, 2) void fused_kernel(
    float* __restrict__ out, const float* __restrict__ x,
    const float* __restrict__ w0, const float* __restrict__ b0,
    const float* __restrict__ w1, const float* __restrict__ b1,
    const float* __restrict__ w2, const float* __restrict__ b2,
    const float* __restrict__ m2q_w0, const float* __restrict__ m2q_b0,
    const float* __restrict__ m2q_w1, const float* __restrict__ m2q_b1,
    const float* __restrict__ m2q_w2, const float* __restrict__ m2q_b2)
{
    __shared__ __align__(16) float W0s[IN_DIMC][OBS_MID];
    __shared__ __align__(16) float W1s[OBS_MID][OBS_MID];
    __shared__ __align__(16) float W2s[OBS_MID][OBS_BN];
    __shared__ float B0s[OBS_MID], B1s[OBS_MID], B2s[OBS_BN];
    __shared__ unsigned short s_qx[8][T_DIM];
    __shared__ int s_prog[8];
    __shared__ __align__(16) float s_ht[8][16];
    __shared__ __align__(16) float s_q1[8][16];
    __shared__ __align__(16) float s_q2[8][16];

    const int tid = threadIdx.x;

    for (int i = tid; i < IN_DIMC * OBS_MID; i += 256) {
        int k = i / OBS_MID, jj = i % OBS_MID;
        W0s[k][jj] = w0[jj * IN_DIMC + k];
    }
    for (int i = tid; i < OBS_MID * OBS_MID; i += 256) {
        int k = i / OBS_MID, jj = i % OBS_MID;
        W1s[k][jj] = w1[jj * OBS_MID + k];
    }
    for (int i = tid; i < OBS_MID * OBS_BN; i += 256) {
        int k = i / OBS_BN, jj = i % OBS_BN;
        W2s[k][jj] = w2[jj * OBS_MID + k];
    }
    if (tid < OBS_MID) { B0s[tid] = b0[tid]; B1s[tid] = b1[tid]; }
    if (tid < OBS_BN)  { B2s[tid] = b2[tid]; }
    if (tid < 8)       { s_prog[tid] = 0; }
    __syncthreads();

    const float thr = g_thr;
    volatile int* prog = s_prog;

    if (tid < 128) {
        // ================= OBS PRODUCER ROLE (warps 0-3) =================
        const int lane = tid & 31;
        const int tl   = lane & 15;
        const int col  = (tid >> 5) * 2 + (lane >> 4);   // 0..7
        const int b    = blockIdx.x * 8 + col;

        for (int chunk = 0; chunk < T_DIM / 16; chunk++) {
            const int t = chunk * 16 + tl;
            const float4* xr4 =
                reinterpret_cast<const float4*>(x + ((size_t)t * B_DIM + b) * IN_DIMC);

            unsigned long long acc[14];
            #pragma unroll
            for (int i = 0; i < 14; i++) acc[i] = 0ull;
            #pragma unroll 2
            for (int k4 = 0; k4 < 16; k4++) {
                float4 xv4 = __ldg(&xr4[k4]);
                float xs[4] = {xv4.x, xv4.y, xv4.z, xv4.w};
                #pragma unroll
                for (int kk = 0; kk < 4; kk++) {
                    unsigned long long xv2 = pack2(xs[kk], xs[kk]);
                    const ulonglong2* wrow =
                        reinterpret_cast<const ulonglong2*>(&W0s[k4 * 4 + kk][0]);
                    #pragma unroll
                    for (int i = 0; i < 7; i++) {
                        ulonglong2 w = wrow[i];
                        ffma2(acc[2 * i],     xv2, w.x);
                        ffma2(acc[2 * i + 1], xv2, w.y);
                    }
                }
            }
            float h[OBS_MID];
            #pragma unroll
            for (int i = 0; i < 14; i++) unpack2(acc[i], h[2 * i], h[2 * i + 1]);
            #pragma unroll
            for (int jj = 0; jj < OBS_MID; jj++) h[jj] = tanhf(h[jj] + B0s[jj]);

            unsigned long long a2[14];
            #pragma unroll
            for (int i = 0; i < 14; i++) a2[i] = 0ull;
            #pragma unroll
            for (int k = 0; k < OBS_MID; k++) {
                unsigned long long xv2 = pack2(h[k], h[k]);
                const ulonglong2* wrow = reinterpret_cast<const ulonglong2*>(&W1s[k][0]);
                #pragma unroll
                for (int i = 0; i < 7; i++) {
                    ulonglong2 w = wrow[i];
                    ffma2(a2[2 * i],     xv2, w.x);
                    ffma2(a2[2 * i + 1], xv2, w.y);
                }
            }
            float h2[OBS_MID];
            #pragma unroll
            for (int i = 0; i < 14; i++) unpack2(a2[i], h2[2 * i], h2[2 * i + 1]);
            #pragma unroll
            for (int jj = 0; jj < OBS_MID; jj++) h2[jj] = tanhf(h2[jj] + B1s[jj]);

            unsigned long long a3[4];
            #pragma unroll
            for (int i = 0; i < 4; i++) a3[i] = 0ull;
            #pragma unroll
            for (int k = 0; k < OBS_MID; k++) {
                unsigned long long xv2 = pack2(h2[k], h2[k]);
                const ulonglong2* wrow = reinterpret_cast<const ulonglong2*>(&W2s[k][0]);
                ulonglong2 w0v = wrow[0];
                ulonglong2 w1v = wrow[1];
                ffma2(a3[0], xv2, w0v.x);
                ffma2(a3[1], xv2, w0v.y);
                ffma2(a3[2], xv2, w1v.x);
                ffma2(a3[3], xv2, w1v.y);
            }
            float v[OBS_BN];
            #pragma unroll
            for (int i = 0; i < 4; i++) unpack2(a3[i], v[2 * i], v[2 * i + 1]);

            int idx = 3280, p = 1;
            #pragma unroll
            for (int jj = 0; jj < OBS_BN; jj++) {
                float a = v[jj] + B2s[jj];
                int d = (a > thr) - (a < -thr);
                idx += d * p;
                p *= 3;
            }
            s_qx[col][t] = (unsigned short)idx;

            __syncwarp();
            if (tl == 0) {
                __threadfence_block();
                prog[col] = chunk + 1;
            }
        }
        return;
    }

    // ================= RECURRENCE ROLE (warps 4-7) =========
    const int rtid = tid - 128;
    const int j  = rtid & 15;
    const int gb = rtid >> 4;
    const int b  = blockIdx.x * 8 + gb;
    const unsigned gmask = (rtid & 16) ? 0xFFFF0000u : 0x0000FFFFu;

    float w0r[16], w1r[16], w2r[16];
    #pragma unroll
    for (int k = 0; k < 16; k++) {
        w0r[k] = m2q_w0[j * 16 + k];
        w1r[k] = m2q_w1[j * 16 + k];
        w2r[k] = m2q_w2[(j & 7) * 16 + k];
    }
    const float b0r = m2q_b0[j];
    const float b1r = m2q_b1[j];
    const float b2r = m2q_b2[j & 7];

    int p3 = 1;
    #pragma unroll
    for (int i = 0; i < 8; i++) if (i < (j & 7)) p3 *= 3;

    while (prog[gb] < 1) __nanosleep(64);
    __threadfence_block();
    int xq = (int)s_qx[gb][0];
    float4 gi = __ldg(&g_GI4[xq * 16 + j]);
    int qp = NQ;

    for (int t = 0; t < T_DIM; t++) {
        // 2-way bucket probe (overlaps the ghm load)
        const unsigned key = (unsigned)qp * 6561u + (unsigned)xq;
        const unsigned tag = key + 1u;
        const unsigned bkt = (key * 2654435761u) & MEMO_BKT_MASK;
        ulonglong2 e = *reinterpret_cast<const ulonglong2*>(&g_memo[bkt * 2]);

        float4 ghm = __ldg(&g_GHM[qp * 16 + j]);   // critical load (miss path)

        float4 gin = gi;
        int xqn = xq;
        if (t + 1 < T_DIM) {
            const int tn = t + 1;
            if ((tn & 15) == 0) {
                const int need = (tn >> 4) + 1;
                if (prog[gb] < need) {
                    while (prog[gb] < need) __nanosleep(64);
                }
                __threadfence_block();
            }
            xqn = (int)s_qx[gb][tn];
            gin = __ldg(&g_GI4[xqn * 16 + j]);
        }

        bool hit0 = ((unsigned)(e.x >> 32) == tag);
        bool hit1 = ((unsigned)(e.y >> 32) == tag);
        int qn;
        if (__all_sync(gmask, hit0 | hit1)) {        // PER-GROUP decision
            qn = (int)(unsigned)((hit0 ? e.x : e.y) & 0xffffffffu);
        } else {
            float r  = sigf(gi.x + ghm.x);
            float z  = sigf(gi.y + ghm.y);
            float n  = tanhf(gi.z + r * ghm.z);
            float ht = (1.0f - z) * n + z * ghm.w;

            s_ht[gb][j] = ht;
            __syncwarp(gmask);

            float a0a = 0.0f, a0b = 0.0f;
            #pragma unroll
            for (int k4 = 0; k4 < 4; k4 += 2) {
                float4 v0 = reinterpret_cast<const float4*>(s_ht[gb])[k4];
                float4 v1 = reinterpret_cast<const float4*>(s_ht[gb])[k4 + 1];
                a0a += w0r[4 * k4 + 0] * v0.x; a0a += w0r[4 * k4 + 1] * v0.y;
                a0a += w0r[4 * k4 + 2] * v0.z; a0a += w0r[4 * k4 + 3] * v0.w;
                a0b += w0r[4 * k4 + 4] * v1.x; a0b += w0r[4 * k4 + 5] * v1.y;
                a0b += w0r[4 * k4 + 6] * v1.z; a0b += w0r[4 * k4 + 7] * v1.w;
            }
            float q1 = tanhf((a0a + a0b) + b0r);
            s_q1[gb][j] = q1;
            __syncwarp(gmask);

            float a1a = 0.0f, a1b = 0.0f;
            #pragma unroll
            for (int k4 = 0; k4 < 4; k4 += 2) {
                float4 v0 = reinterpret_cast<const float4*>(s_q1[gb])[k4];
                float4 v1 = reinterpret_cast<const float4*>(s_q1[gb])[k4 + 1];
                a1a += w1r[4 * k4 + 0] * v0.x; a1a += w1r[4 * k4 + 1] * v0.y;
                a1a += w1r[4 * k4 + 2] * v0.z; a1a += w1r[4 * k4 + 3] * v0.w;
                a1b += w1r[4 * k4 + 4] * v1.x; a1b += w1r[4 * k4 + 5] * v1.y;
                a1b += w1r[4 * k4 + 6] * v1.z; a1b += w1r[4 * k4 + 7] * v1.w;
            }
            float q2v = tanhf((a1a + a1b) + b1r);
            s_q2[gb][j] = q2v;
            __syncwarp(gmask);

            float a2a = 0.0f, a2b = 0.0f;
            #pragma unroll
            for (int k4 = 0; k4 < 4; k4 += 2) {
                float4 v0 = reinterpret_cast<const float4*>(s_q2[gb])[k4];
                float4 v1 = reinterpret_cast<const float4*>(s_q2[gb])[k4 + 1];
                a2a += w2r[4 * k4 + 0] * v0.x; a2a += w2r[4 * k4 + 1] * v0.y;
                a2a += w2r[4 * k4 + 2] * v0.z; a2a += w2r[4 * k4 + 3] * v0.w;
                a2b += w2r[4 * k4 + 4] * v1.x; a2b += w2r[4 * k4 + 5] * v1.y;
                a2b += w2r[4 * k4 + 6] * v1.z; a2b += w2r[4 * k4 + 7] * v1.w;
            }
            float v = (a2a + a2b) + b2r;

            int d = (v > thr) - (v < -thr);
            int s = __reduce_add_sync(gmask, d * p3);   // 16-lane sum = 2*code
            qn = 3280 + (s >> 1);

            if ((rtid & 15) == 0) {
                unsigned long long ent =
                    (((unsigned long long)tag) << 32) | (unsigned)qn;
                unsigned t0 = (unsigned)(e.x >> 32);
                int slot = (t0 == 0u || t0 == tag) ? 0 : 1;
                g_memo[bkt * 2 + slot] = ent;
            }
        }

        out[((size_t)(t * B_DIM + b)) * 16 + j] = __ldg(&g_OUT[qn * 16 + j]);
        qp = qn;
        gi = gin;
        xq = xqn;
    }
}

// ---------------------------------------------------------------------------
extern "C" void kernel_launch(void* const* d_in, const int* in_sizes, int n_in,
                              void* d_out, int out_size)
{
    (void)in_sizes; (void)n_in; (void)out_size;
    const float* x       = (const float*)d_in[0];
    const float* obs_w0  = (const float*)d_in[1];
    const float* obs_b0  = (const float*)d_in[2];
    const float* obs_w1  = (const float*)d_in[3];
    const float* obs_b1  = (const float*)d_in[4];
    const float* obs_w2  = (const float*)d_in[5];
    const float* obs_b2  = (const float*)d_in[6];
    const float* gru_wih = (const float*)d_in[7];
    const float* gru_whh = (const float*)d_in[8];
    const float* gru_bih = (const float*)d_in[9];
    const float* gru_bhh = (const float*)d_in[10];
    const float* m2q_w0  = (const float*)d_in[11];
    const float* m2q_b0  = (const float*)d_in[12];
    const float* m2q_w1  = (const float*)d_in[13];
    const float* m2q_b1  = (const float*)d_in[14];
    const float* m2q_w2  = (const float*)d_in[15];
    const float* m2q_b2  = (const float*)d_in[16];
    const float* q2m_w0  = (const float*)d_in[17];
    const float* q2m_b0  = (const float*)d_in[18];
    const float* q2m_w1  = (const float*)d_in[19];
    const float* q2m_b1  = (const float*)d_in[20];
    const float* q2m_w2  = (const float*)d_in[21];
    const float* q2m_b2  = (const float*)d_in[22];
    const float* act_w   = (const float*)d_in[23];
    const float* act_b   = (const float*)d_in[24];
    float* out = (float*)d_out;

    memo_clear<<<MEMO_BKTS / 256, 256>>>();   // per-launch: identical work every call
    setup_all<<<(NQ + 1 + 15) / 16, 256>>>(
        q2m_w0, q2m_b0, q2m_w1, q2m_b1, q2m_w2, q2m_b2,
        act_w, act_b, gru_wih, gru_whh, gru_bih, gru_bhh);
    fused_kernel<<<B_DIM / 8, 256>>>(
        out, x, obs_w0, obs_b0, obs_w1, obs_b1, obs_w2, obs_b2,
        m2q_w0, m2q_b0, m2q_w1, m2q_b1, m2q_w2, m2q_b2);
}

// round 11
// speedup vs baseline: 1.5130x; 1.5130x over previous
#include <cuda_runtime.h>
#include <math.h>

#define T_DIM   512
#define B_DIM   2048
#define IN_DIMC 64
#define OBS_MID 28
#define OBS_BN  8
#define NQ      6561   /* 3^8 */

#define MEMO_BKT_BITS 21
#define MEMO_BKTS     (1u << MEMO_BKT_BITS)   /* 2M buckets x 16B = 32MB */
#define MEMO_BKT_MASK (MEMO_BKTS - 1u)

// ---- persistent device scratch ----
__device__ float4 g_GHM[(NQ + 1) * 16];   // (gh_r, gh_z, gh_n, m) per state, per lane
__device__ float4 g_GI4[NQ * 16];         // (gi_r, gi_z, gi_n, 0) per obs code, per lane
__device__ float  g_OUT[NQ * 16];         // tanh(M[q] @ act_w^T + act_b)
__device__ float  g_thr;                  // ternary decision threshold
__device__ __align__(16) unsigned long long g_memo[MEMO_BKTS * 2]; // 2-way buckets

__device__ __forceinline__ float sigf(float x) {
    return 0.5f + 0.5f * tanhf(0.5f * x);
}

// f32x2 packed-FMA helpers
__device__ __forceinline__ unsigned long long pack2(float a, float b) {
    unsigned long long r;
    asm("mov.b64 %0, {%1, %2};" : "=l"(r) : "f"(a), "f"(b));
    return r;
}
__device__ __forceinline__ void unpack2(unsigned long long v, float& a, float& b) {
    asm("mov.b64 {%0, %1}, %2;" : "=f"(a), "=f"(b) : "l"(v));
}
__device__ __forceinline__ void ffma2(unsigned long long& d, unsigned long long a,
                                      unsigned long long b) {
    asm("fma.rn.f32x2 %0, %1, %2, %0;" : "+l"(d) : "l"(a), "l"(b));
}

// ---------------------------------------------------------------------------
__global__ void memo_clear() {
    reinterpret_cast<ulonglong2*>(g_memo)[blockIdx.x * blockDim.x + threadIdx.x] =
        make_ulonglong2(0ull, 0ull);
}

// ---------------------------------------------------------------------------
// Setup: 16-lane groups, one state code per group, shfl exchanges.
// ---------------------------------------------------------------------------
__global__ __launch_bounds__(256) void setup_all(
    const float* __restrict__ q2m_w0, const float* __restrict__ q2m_b0,
    const float* __restrict__ q2m_w1, const float* __restrict__ q2m_b1,
    const float* __restrict__ q2m_w2, const float* __restrict__ q2m_b2,
    const float* __restrict__ act_w,  const float* __restrict__ act_b,
    const float* __restrict__ wih, const float* __restrict__ whh,
    const float* __restrict__ bih, const float* __restrict__ bhh)
{
    const int tid = threadIdx.x;
    const int j   = tid & 15;
    int g = blockIdx.x * 16 + (tid >> 4);
    if (blockIdx.x == 0 && tid == 0) {
        float lo = 0.0f, hi = 2.0f;
        for (int it = 0; it < 80; it++) {
            float mid = 0.5f * (lo + hi);
            if (mid <= lo || mid >= hi) break;
            float s = 1.5f * tanhf(mid) + 0.5f * tanhf(-3.0f * mid);
            if (s > 0.5f) hi = mid; else lo = mid;
        }
        g_thr = lo;
    }
    bool real = (g < NQ);
    if (g > NQ) { g = NQ; real = false; }

    float q[8];
    if (real) {
        int r = g;
        #pragma unroll
        for (int i = 0; i < 8; i++) { q[i] = (float)(r % 3 - 1); r /= 3; }
    }

    float m2j = 0.0f;
    if (real) {
        float a = 0.0f;
        #pragma unroll
        for (int k = 0; k < 8; k++) a += q2m_w0[j * 8 + k] * q[k];
        float m0j = tanhf(a + q2m_b0[j]);

        float a1 = 0.0f;
        #pragma unroll
        for (int k = 0; k < 16; k++)
            a1 += q2m_w1[j * 16 + k] * __shfl_sync(0xffffffffu, m0j, k, 16);
        float m1j = tanhf(a1 + q2m_b1[j]);

        float a2 = 0.0f;
        #pragma unroll
        for (int k = 0; k < 16; k++)
            a2 += q2m_w2[j * 16 + k] * __shfl_sync(0xffffffffu, m1j, k, 16);
        m2j = tanhf(a2 + q2m_b2[j]);

        float ao = 0.0f;
        #pragma unroll
        for (int k = 0; k < 16; k++)
            ao += act_w[j * 16 + k] * __shfl_sync(0xffffffffu, m2j, k, 16);
        g_OUT[g * 16 + j] = tanhf(ao + act_b[j]);
    }

    {
        float ar = 0.0f, az = 0.0f, an = 0.0f;
        #pragma unroll
        for (int k = 0; k < 16; k++) {
            float mk = __shfl_sync(0xffffffffu, m2j, k, 16);
            ar += mk * whh[j * 16 + k];
            az += mk * whh[(16 + j) * 16 + k];
            an += mk * whh[(32 + j) * 16 + k];
        }
        g_GHM[g * 16 + j] = make_float4(ar + bhh[j], az + bhh[16 + j],
                                        an + bhh[32 + j], m2j);
    }
    if (real) {
        float ar = 0.0f, az = 0.0f, an = 0.0f;
        #pragma unroll
        for (int k = 0; k < 8; k++) {
            ar += q[k] * wih[j * 8 + k];
            az += q[k] * wih[(16 + j) * 8 + k];
            an += q[k] * wih[(32 + j) * 8 + k];
        }
        g_GI4[g * 16 + j] = make_float4(ar + bih[j], az + bih[16 + j],
                                        an + bih[32 + j], 0.0f);
    }
}

// ---------------------------------------------------------------------------
// Fused kernel: warps 0-3 = obs producer, warps 4-7 = recurrence with
// per-launch transition memoization (2-way hashed buckets, warp-wide hit
// decision). x is streamed with .cs so L1 stays dedicated to the chain
// loads (g_GHM + hot memo buckets).
// ---------------------------------------------------------------------------
__global__ __launch_bounds__(256, 2) void fused_kernel(
    float* __restrict__ out, const float* __restrict__ x,
    const float* __restrict__ w0, const float* __restrict__ b0,
    const float* __restrict__ w1, const float* __restrict__ b1,
    const float* __restrict__ w2, const float* __restrict__ b2,
    const float* __restrict__ m2q_w0, const float* __restrict__ m2q_b0,
    const float* __restrict__ m2q_w1, const float* __restrict__ m2q_b1,
    const float* __restrict__ m2q_w2, const float* __restrict__ m2q_b2)
{
    __shared__ __align__(16) float W0s[IN_DIMC][OBS_MID];
    __shared__ __align__(16) float W1s[OBS_MID][OBS_MID];
    __shared__ __align__(16) float W2s[OBS_MID][OBS_BN];
    __shared__ float B0s[OBS_MID], B1s[OBS_MID], B2s[OBS_BN];
    __shared__ unsigned short s_qx[8][T_DIM];
    __shared__ int s_prog[8];
    __shared__ __align__(16) float s_ht[8][16];
    __shared__ __align__(16) float s_q1[8][16];
    __shared__ __align__(16) float s_q2[8][16];

    const int tid = threadIdx.x;

    for (int i = tid; i < IN_DIMC * OBS_MID; i += 256) {
        int k = i / OBS_MID, jj = i % OBS_MID;
        W0s[k][jj] = w0[jj * IN_DIMC + k];
    }
    for (int i = tid; i < OBS_MID * OBS_MID; i += 256) {
        int k = i / OBS_MID, jj = i % OBS_MID;
        W1s[k][jj] = w1[jj * OBS_MID + k];
    }
    for (int i = tid; i < OBS_MID * OBS_BN; i += 256) {
        int k = i / OBS_BN, jj = i % OBS_BN;
        W2s[k][jj] = w2[jj * OBS_MID + k];
    }
    if (tid < OBS_MID) { B0s[tid] = b0[tid]; B1s[tid] = b1[tid]; }
    if (tid < OBS_BN)  { B2s[tid] = b2[tid]; }
    if (tid < 8)       { s_prog[tid] = 0; }
    __syncthreads();

    const float thr = g_thr;
    volatile int* prog = s_prog;

    if (tid < 128) {
        // ================= OBS PRODUCER ROLE (warps 0-3) =================
        const int lane = tid & 31;
        const int tl   = lane & 15;
        const int col  = (tid >> 5) * 2 + (lane >> 4);   // 0..7
        const int b    = blockIdx.x * 8 + col;

        for (int chunk = 0; chunk < T_DIM / 16; chunk++) {
            const int t = chunk * 16 + tl;
            const float4* xr4 =
                reinterpret_cast<const float4*>(x + ((size_t)t * B_DIM + b) * IN_DIMC);

            unsigned long long acc[14];
            #pragma unroll
            for (int i = 0; i < 14; i++) acc[i] = 0ull;
            #pragma unroll 2
            for (int k4 = 0; k4 < 16; k4++) {
                float4 xv4 = __ldcs(&xr4[k4]);   // streaming: keep x out of L1
                float xs[4] = {xv4.x, xv4.y, xv4.z, xv4.w};
                #pragma unroll
                for (int kk = 0; kk < 4; kk++) {
                    unsigned long long xv2 = pack2(xs[kk], xs[kk]);
                    const ulonglong2* wrow =
                        reinterpret_cast<const ulonglong2*>(&W0s[k4 * 4 + kk][0]);
                    #pragma unroll
                    for (int i = 0; i < 7; i++) {
                        ulonglong2 w = wrow[i];
                        ffma2(acc[2 * i],     xv2, w.x);
                        ffma2(acc[2 * i + 1], xv2, w.y);
                    }
                }
            }
            float h[OBS_MID];
            #pragma unroll
            for (int i = 0; i < 14; i++) unpack2(acc[i], h[2 * i], h[2 * i + 1]);
            #pragma unroll
            for (int jj = 0; jj < OBS_MID; jj++) h[jj] = tanhf(h[jj] + B0s[jj]);

            unsigned long long a2[14];
            #pragma unroll
            for (int i = 0; i < 14; i++) a2[i] = 0ull;
            #pragma unroll
            for (int k = 0; k < OBS_MID; k++) {
                unsigned long long xv2 = pack2(h[k], h[k]);
                const ulonglong2* wrow = reinterpret_cast<const ulonglong2*>(&W1s[k][0]);
                #pragma unroll
                for (int i = 0; i < 7; i++) {
                    ulonglong2 w = wrow[i];
                    ffma2(a2[2 * i],     xv2, w.x);
                    ffma2(a2[2 * i + 1], xv2, w.y);
                }
            }
            float h2[OBS_MID];
            #pragma unroll
            for (int i = 0; i < 14; i++) unpack2(a2[i], h2[2 * i], h2[2 * i + 1]);
            #pragma unroll
            for (int jj = 0; jj < OBS_MID; jj++) h2[jj] = tanhf(h2[jj] + B1s[jj]);

            unsigned long long a3[4];
            #pragma unroll
            for (int i = 0; i < 4; i++) a3[i] = 0ull;
            #pragma unroll
            for (int k = 0; k < OBS_MID; k++) {
                unsigned long long xv2 = pack2(h2[k], h2[k]);
                const ulonglong2* wrow = reinterpret_cast<const ulonglong2*>(&W2s[k][0]);
                ulonglong2 w0v = wrow[0];
                ulonglong2 w1v = wrow[1];
                ffma2(a3[0], xv2, w0v.x);
                ffma2(a3[1], xv2, w0v.y);
                ffma2(a3[2], xv2, w1v.x);
                ffma2(a3[3], xv2, w1v.y);
            }
            float v[OBS_BN];
            #pragma unroll
            for (int i = 0; i < 4; i++) unpack2(a3[i], v[2 * i], v[2 * i + 1]);

            int idx = 3280, p = 1;
            #pragma unroll
            for (int jj = 0; jj < OBS_BN; jj++) {
                float a = v[jj] + B2s[jj];
                int d = (a > thr) - (a < -thr);
                idx += d * p;
                p *= 3;
            }
            s_qx[col][t] = (unsigned short)idx;

            __syncwarp();
            if (tl == 0) {
                __threadfence_block();
                prog[col] = chunk + 1;
            }
        }
        return;
    }

    // ================= RECURRENCE ROLE (warps 4-7) =========
    const int rtid = tid - 128;
    const int j  = rtid & 15;
    const int gb = rtid >> 4;
    const int b  = blockIdx.x * 8 + gb;
    const unsigned gmask = (rtid & 16) ? 0xFFFF0000u : 0x0000FFFFu;

    float w0r[16], w1r[16], w2r[16];
    #pragma unroll
    for (int k = 0; k < 16; k++) {
        w0r[k] = m2q_w0[j * 16 + k];
        w1r[k] = m2q_w1[j * 16 + k];
        w2r[k] = m2q_w2[(j & 7) * 16 + k];
    }
    const float b0r = m2q_b0[j];
    const float b1r = m2q_b1[j];
    const float b2r = m2q_b2[j & 7];

    int p3 = 1;
    #pragma unroll
    for (int i = 0; i < 8; i++) if (i < (j & 7)) p3 *= 3;

    while (prog[gb] < 1) __nanosleep(64);
    __threadfence_block();
    int xq = (int)s_qx[gb][0];
    float4 gi = __ldg(&g_GI4[xq * 16 + j]);
    int qp = NQ;

    for (int t = 0; t < T_DIM; t++) {
        // 2-way bucket probe (overlaps the ghm load)
        const unsigned key = (unsigned)qp * 6561u + (unsigned)xq;
        const unsigned tag = key + 1u;
        const unsigned bkt = (key * 2654435761u) & MEMO_BKT_MASK;
        ulonglong2 e = *reinterpret_cast<const ulonglong2*>(&g_memo[bkt * 2]);

        float4 ghm = __ldg(&g_GHM[qp * 16 + j]);   // critical load (miss path)

        float4 gin = gi;
        int xqn = xq;
        if (t + 1 < T_DIM) {
            const int tn = t + 1;
            if ((tn & 15) == 0) {
                const int need = (tn >> 4) + 1;
                if (prog[gb] < need) {
                    while (prog[gb] < need) __nanosleep(64);
                }
                __threadfence_block();
            }
            xqn = (int)s_qx[gb][tn];
            gin = __ldg(&g_GI4[xqn * 16 + j]);
        }

        bool hit0 = ((unsigned)(e.x >> 32) == tag);
        bool hit1 = ((unsigned)(e.y >> 32) == tag);
        int qn;
        if (__all_sync(0xffffffffu, hit0 | hit1)) {   // warp-wide decision
            qn = (int)(unsigned)((hit0 ? e.x : e.y) & 0xffffffffu);
        } else {
            float r  = sigf(gi.x + ghm.x);
            float z  = sigf(gi.y + ghm.y);
            float n  = tanhf(gi.z + r * ghm.z);
            float ht = (1.0f - z) * n + z * ghm.w;

            s_ht[gb][j] = ht;
            __syncwarp();

            float a0a = 0.0f, a0b = 0.0f;
            #pragma unroll
            for (int k4 = 0; k4 < 4; k4 += 2) {
                float4 v0 = reinterpret_cast<const float4*>(s_ht[gb])[k4];
                float4 v1 = reinterpret_cast<const float4*>(s_ht[gb])[k4 + 1];
                a0a += w0r[4 * k4 + 0] * v0.x; a0a += w0r[4 * k4 + 1] * v0.y;
                a0a += w0r[4 * k4 + 2] * v0.z; a0a += w0r[4 * k4 + 3] * v0.w;
                a0b += w0r[4 * k4 + 4] * v1.x; a0b += w0r[4 * k4 + 5] * v1.y;
                a0b += w0r[4 * k4 + 6] * v1.z; a0b += w0r[4 * k4 + 7] * v1.w;
            }
            float q1 = tanhf((a0a + a0b) + b0r);
            s_q1[gb][j] = q1;
            __syncwarp();

            float a1a = 0.0f, a1b = 0.0f;
            #pragma unroll
            for (int k4 = 0; k4 < 4; k4 += 2) {
                float4 v0 = reinterpret_cast<const float4*>(s_q1[gb])[k4];
                float4 v1 = reinterpret_cast<const float4*>(s_q1[gb])[k4 + 1];
                a1a += w1r[4 * k4 + 0] * v0.x; a1a += w1r[4 * k4 + 1] * v0.y;
                a1a += w1r[4 * k4 + 2] * v0.z; a1a += w1r[4 * k4 + 3] * v0.w;
                a1b += w1r[4 * k4 + 4] * v1.x; a1b += w1r[4 * k4 + 5] * v1.y;
                a1b += w1r[4 * k4 + 6] * v1.z; a1b += w1r[4 * k4 + 7] * v1.w;
            }
            float q2v = tanhf((a1a + a1b) + b1r);
            s_q2[gb][j] = q2v;
            __syncwarp();

            float a2a = 0.0f, a2b = 0.0f;
            #pragma unroll
            for (int k4 = 0; k4 < 4; k4 += 2) {
                float4 v0 = reinterpret_cast<const float4*>(s_q2[gb])[k4];
                float4 v1 = reinterpret_cast<const float4*>(s_q2[gb])[k4 + 1];
                a2a += w2r[4 * k4 + 0] * v0.x; a2a += w2r[4 * k4 + 1] * v0.y;
                a2a += w2r[4 * k4 + 2] * v0.z; a2a += w2r[4 * k4 + 3] * v0.w;
                a2b += w2r[4 * k4 + 4] * v1.x; a2b += w2r[4 * k4 + 5] * v1.y;
                a2b += w2r[4 * k4 + 6] * v1.z; a2b += w2r[4 * k4 + 7] * v1.w;
            }
            float v = (a2a + a2b) + b2r;

            int d = (v > thr) - (v < -thr);
            int s = __reduce_add_sync(gmask, d * p3);   // 16-lane sum = 2*code
            qn = 3280 + (s >> 1);

            if ((rtid & 15) == 0) {
                unsigned long long ent =
                    (((unsigned long long)tag) << 32) | (unsigned)qn;
                unsigned t0 = (unsigned)(e.x >> 32);
                int slot = (t0 == 0u || t0 == tag) ? 0 : 1;
                g_memo[bkt * 2 + slot] = ent;
            }
        }

        out[((size_t)(t * B_DIM + b)) * 16 + j] = __ldg(&g_OUT[qn * 16 + j]);
        qp = qn;
        gi = gin;
        xq = xqn;
    }
}

// ---------------------------------------------------------------------------
extern "C" void kernel_launch(void* const* d_in, const int* in_sizes, int n_in,
                              void* d_out, int out_size)
{
    (void)in_sizes; (void)n_in; (void)out_size;
    const float* x       = (const float*)d_in[0];
    const float* obs_w0  = (const float*)d_in[1];
    const float* obs_b0  = (const float*)d_in[2];
    const float* obs_w1  = (const float*)d_in[3];
    const float* obs_b1  = (const float*)d_in[4];
    const float* obs_w2  = (const float*)d_in[5];
    const float* obs_b2  = (const float*)d_in[6];
    const float* gru_wih = (const float*)d_in[7];
    const float* gru_whh = (const float*)d_in[8];
    const float* gru_bih = (const float*)d_in[9];
    const float* gru_bhh = (const float*)d_in[10];
    const float* m2q_w0  = (const float*)d_in[11];
    const float* m2q_b0  = (const float*)d_in[12];
    const float* m2q_w1  = (const float*)d_in[13];
    const float* m2q_b1  = (const float*)d_in[14];
    const float* m2q_w2  = (const float*)d_in[15];
    const float* m2q_b2  = (const float*)d_in[16];
    const float* q2m_w0  = (const float*)d_in[17];
    const float* q2m_b0  = (const float*)d_in[18];
    const float* q2m_w1  = (const float*)d_in[19];
    const float* q2m_b1  = (const float*)d_in[20];
    const float* q2m_w2  = (const float*)d_in[21];
    const float* q2m_b2  = (const float*)d_in[22];
    const float* act_w   = (const float*)d_in[23];
    const float* act_b   = (const float*)d_in[24];
    float* out = (float*)d_out;

    memo_clear<<<MEMO_BKTS / 256, 256>>>();   // per-launch: identical work every call
    setup_all<<<(NQ + 1 + 15) / 16, 256>>>(
        q2m_w0, q2m_b0, q2m_w1, q2m_b1, q2m_w2, q2m_b2,
        act_w, act_b, gru_wih, gru_whh, gru_bih, gru_bhh);
    fused_kernel<<<B_DIM / 8, 256>>>(
        out, x, obs_w0, obs_b0, obs_w1, obs_b1, obs_w2, obs_b2,
        m2q_w0, m2q_b0, m2q_w1, m2q_b1, m2q_w2, m2q_b2);
}

// round 12
// speedup vs baseline: 1.7302x; 1.1435x over previous
#include <cuda_runtime.h>
#include <math.h>

#define T_DIM   512
#define B_DIM   2048
#define IN_DIMC 64
#define OBS_MID 28
#define OBS_BN  8
#define NQ      6561   /* 3^8 */

#define COLS_PB 14                      /* columns per block */
#define NBLK    ((B_DIM + COLS_PB - 1) / COLS_PB)   /* 147 <= 148 SMs */
#define THREADS (COLS_PB * 32)          /* 448: 7 obs warps + 7 recur warps */

#define MEMO_BKT_BITS 21
#define MEMO_BKTS     (1u << MEMO_BKT_BITS)   /* 2M buckets x 16B = 32MB */
#define MEMO_BKT_MASK (MEMO_BKTS - 1u)

// ---- persistent device scratch ----
__device__ float4 g_GHM[(NQ + 1) * 16];   // (gh_r, gh_z, gh_n, m) per state, per lane
__device__ float4 g_GI4[NQ * 16];         // (gi_r, gi_z, gi_n, 0) per obs code, per lane
__device__ float  g_OUT[NQ * 16];         // tanh(M[q] @ act_w^T + act_b)
__device__ float  g_thr;                  // ternary decision threshold
__device__ __align__(16) unsigned long long g_memo[MEMO_BKTS * 2]; // 2-way buckets

__device__ __forceinline__ float sigf(float x) {
    return 0.5f + 0.5f * tanhf(0.5f * x);
}

// f32x2 packed-FMA helpers
__device__ __forceinline__ unsigned long long pack2(float a, float b) {
    unsigned long long r;
    asm("mov.b64 %0, {%1, %2};" : "=l"(r) : "f"(a), "f"(b));
    return r;
}
__device__ __forceinline__ void unpack2(unsigned long long v, float& a, float& b) {
    asm("mov.b64 {%0, %1}, %2;" : "=f"(a), "=f"(b) : "l"(v));
}
__device__ __forceinline__ void ffma2(unsigned long long& d, unsigned long long a,
                                      unsigned long long b) {
    asm("fma.rn.f32x2 %0, %1, %2, %0;" : "+l"(d) : "l"(a), "l"(b));
}

// ---------------------------------------------------------------------------
__global__ void memo_clear() {
    reinterpret_cast<ulonglong2*>(g_memo)[blockIdx.x * blockDim.x + threadIdx.x] =
        make_ulonglong2(0ull, 0ull);
}

// ---------------------------------------------------------------------------
// Setup: 16-lane groups, one state code per group, shfl exchanges.
// ---------------------------------------------------------------------------
__global__ __launch_bounds__(256) void setup_all(
    const float* __restrict__ q2m_w0, const float* __restrict__ q2m_b0,
    const float* __restrict__ q2m_w1, const float* __restrict__ q2m_b1,
    const float* __restrict__ q2m_w2, const float* __restrict__ q2m_b2,
    const float* __restrict__ act_w,  const float* __restrict__ act_b,
    const float* __restrict__ wih, const float* __restrict__ whh,
    const float* __restrict__ bih, const float* __restrict__ bhh)
{
    const int tid = threadIdx.x;
    const int j   = tid & 15;
    int g = blockIdx.x * 16 + (tid >> 4);
    if (blockIdx.x == 0 && tid == 0) {
        float lo = 0.0f, hi = 2.0f;
        for (int it = 0; it < 80; it++) {
            float mid = 0.5f * (lo + hi);
            if (mid <= lo || mid >= hi) break;
            float s = 1.5f * tanhf(mid) + 0.5f * tanhf(-3.0f * mid);
            if (s > 0.5f) hi = mid; else lo = mid;
        }
        g_thr = lo;
    }
    bool real = (g < NQ);
    if (g > NQ) { g = NQ; real = false; }

    float q[8];
    if (real) {
        int r = g;
        #pragma unroll
        for (int i = 0; i < 8; i++) { q[i] = (float)(r % 3 - 1); r /= 3; }
    }

    float m2j = 0.0f;
    if (real) {
        float a = 0.0f;
        #pragma unroll
        for (int k = 0; k < 8; k++) a += q2m_w0[j * 8 + k] * q[k];
        float m0j = tanhf(a + q2m_b0[j]);

        float a1 = 0.0f;
        #pragma unroll
        for (int k = 0; k < 16; k++)
            a1 += q2m_w1[j * 16 + k] * __shfl_sync(0xffffffffu, m0j, k, 16);
        float m1j = tanhf(a1 + q2m_b1[j]);

        float a2 = 0.0f;
        #pragma unroll
        for (int k = 0; k < 16; k++)
            a2 += q2m_w2[j * 16 + k] * __shfl_sync(0xffffffffu, m1j, k, 16);
        m2j = tanhf(a2 + q2m_b2[j]);

        float ao = 0.0f;
        #pragma unroll
        for (int k = 0; k < 16; k++)
            ao += act_w[j * 16 + k] * __shfl_sync(0xffffffffu, m2j, k, 16);
        g_OUT[g * 16 + j] = tanhf(ao + act_b[j]);
    }

    {
        float ar = 0.0f, az = 0.0f, an = 0.0f;
        #pragma unroll
        for (int k = 0; k < 16; k++) {
            float mk = __shfl_sync(0xffffffffu, m2j, k, 16);
            ar += mk * whh[j * 16 + k];
            az += mk * whh[(16 + j) * 16 + k];
            an += mk * whh[(32 + j) * 16 + k];
        }
        g_GHM[g * 16 + j] = make_float4(ar + bhh[j], az + bhh[16 + j],
                                        an + bhh[32 + j], m2j);
    }
    if (real) {
        float ar = 0.0f, az = 0.0f, an = 0.0f;
        #pragma unroll
        for (int k = 0; k < 8; k++) {
            ar += q[k] * wih[j * 8 + k];
            az += q[k] * wih[(16 + j) * 8 + k];
            an += q[k] * wih[(32 + j) * 8 + k];
        }
        g_GI4[g * 16 + j] = make_float4(ar + bih[j], az + bih[16 + j],
                                        an + bih[32 + j], 0.0f);
    }
}

// ---------------------------------------------------------------------------
// Fused kernel, load-balanced: 147 blocks x 448 threads = 1 block/SM,
// 14 columns per SM (was 16 on the doubled SMs / 8 on the rest).
// Warps 0-6 = obs producer (2 cols each), warps 7-13 = recurrence (2 cols).
// Inner code identical to the round-9 champion.
// ---------------------------------------------------------------------------
__global__ __launch_bounds__(THREADS, 1) void fused_kernel(
    float* __restrict__ out, const float* __restrict__ x,
    const float* __restrict__ w0, const float* __restrict__ b0,
    const float* __restrict__ w1, const float* __restrict__ b1,
    const float* __restrict__ w2, const float* __restrict__ b2,
    const float* __restrict__ m2q_w0, const float* __restrict__ m2q_b0,
    const float* __restrict__ m2q_w1, const float* __restrict__ m2q_b1,
    const float* __restrict__ m2q_w2, const float* __restrict__ m2q_b2)
{
    __shared__ __align__(16) float W0s[IN_DIMC][OBS_MID];
    __shared__ __align__(16) float W1s[OBS_MID][OBS_MID];
    __shared__ __align__(16) float W2s[OBS_MID][OBS_BN];
    __shared__ float B0s[OBS_MID], B1s[OBS_MID], B2s[OBS_BN];
    __shared__ unsigned short s_qx[COLS_PB][T_DIM];
    __shared__ int s_prog[COLS_PB];
    __shared__ __align__(16) float s_ht[COLS_PB][16];
    __shared__ __align__(16) float s_q1[COLS_PB][16];
    __shared__ __align__(16) float s_q2[COLS_PB][16];

    const int tid = threadIdx.x;

    for (int i = tid; i < IN_DIMC * OBS_MID; i += THREADS) {
        int k = i / OBS_MID, jj = i % OBS_MID;
        W0s[k][jj] = w0[jj * IN_DIMC + k];
    }
    for (int i = tid; i < OBS_MID * OBS_MID; i += THREADS) {
        int k = i / OBS_MID, jj = i % OBS_MID;
        W1s[k][jj] = w1[jj * OBS_MID + k];
    }
    for (int i = tid; i < OBS_MID * OBS_BN; i += THREADS) {
        int k = i / OBS_BN, jj = i % OBS_BN;
        W2s[k][jj] = w2[jj * OBS_MID + k];
    }
    if (tid < OBS_MID)  { B0s[tid] = b0[tid]; B1s[tid] = b1[tid]; }
    if (tid < OBS_BN)   { B2s[tid] = b2[tid]; }
    if (tid < COLS_PB)  { s_prog[tid] = 0; }
    __syncthreads();

    const float thr = g_thr;
    volatile int* prog = s_prog;

    if (tid < COLS_PB * 16) {
        // ================= OBS PRODUCER ROLE (warps 0-6) =================
        const int lane = tid & 31;
        const int tl   = lane & 15;
        const int col  = (tid >> 5) * 2 + (lane >> 4);   // 0..13
        const int breal = blockIdx.x * COLS_PB + col;
        const int b    = (breal < B_DIM) ? breal : (B_DIM - 1);   // clamp tail

        for (int chunk = 0; chunk < T_DIM / 16; chunk++) {
            const int t = chunk * 16 + tl;
            const float4* xr4 =
                reinterpret_cast<const float4*>(x + ((size_t)t * B_DIM + b) * IN_DIMC);

            unsigned long long acc[14];
            #pragma unroll
            for (int i = 0; i < 14; i++) acc[i] = 0ull;
            #pragma unroll 2
            for (int k4 = 0; k4 < 16; k4++) {
                float4 xv4 = __ldg(&xr4[k4]);
                float xs[4] = {xv4.x, xv4.y, xv4.z, xv4.w};
                #pragma unroll
                for (int kk = 0; kk < 4; kk++) {
                    unsigned long long xv2 = pack2(xs[kk], xs[kk]);
                    const ulonglong2* wrow =
                        reinterpret_cast<const ulonglong2*>(&W0s[k4 * 4 + kk][0]);
                    #pragma unroll
                    for (int i = 0; i < 7; i++) {
                        ulonglong2 w = wrow[i];
                        ffma2(acc[2 * i],     xv2, w.x);
                        ffma2(acc[2 * i + 1], xv2, w.y);
                    }
                }
            }
            float h[OBS_MID];
            #pragma unroll
            for (int i = 0; i < 14; i++) unpack2(acc[i], h[2 * i], h[2 * i + 1]);
            #pragma unroll
            for (int jj = 0; jj < OBS_MID; jj++) h[jj] = tanhf(h[jj] + B0s[jj]);

            unsigned long long a2[14];
            #pragma unroll
            for (int i = 0; i < 14; i++) a2[i] = 0ull;
            #pragma unroll
            for (int k = 0; k < OBS_MID; k++) {
                unsigned long long xv2 = pack2(h[k], h[k]);
                const ulonglong2* wrow = reinterpret_cast<const ulonglong2*>(&W1s[k][0]);
                #pragma unroll
                for (int i = 0; i < 7; i++) {
                    ulonglong2 w = wrow[i];
                    ffma2(a2[2 * i],     xv2, w.x);
                    ffma2(a2[2 * i + 1], xv2, w.y);
                }
            }
            float h2[OBS_MID];
            #pragma unroll
            for (int i = 0; i < 14; i++) unpack2(a2[i], h2[2 * i], h2[2 * i + 1]);
            #pragma unroll
            for (int jj = 0; jj < OBS_MID; jj++) h2[jj] = tanhf(h2[jj] + B1s[jj]);

            unsigned long long a3[4];
            #pragma unroll
            for (int i = 0; i < 4; i++) a3[i] = 0ull;
            #pragma unroll
            for (int k = 0; k < OBS_MID; k++) {
                unsigned long long xv2 = pack2(h2[k], h2[k]);
                const ulonglong2* wrow = reinterpret_cast<const ulonglong2*>(&W2s[k][0]);
                ulonglong2 w0v = wrow[0];
                ulonglong2 w1v = wrow[1];
                ffma2(a3[0], xv2, w0v.x);
                ffma2(a3[1], xv2, w0v.y);
                ffma2(a3[2], xv2, w1v.x);
                ffma2(a3[3], xv2, w1v.y);
            }
            float v[OBS_BN];
            #pragma unroll
            for (int i = 0; i < 4; i++) unpack2(a3[i], v[2 * i], v[2 * i + 1]);

            int idx = 3280, p = 1;
            #pragma unroll
            for (int jj = 0; jj < OBS_BN; jj++) {
                float a = v[jj] + B2s[jj];
                int d = (a > thr) - (a < -thr);
                idx += d * p;
                p *= 3;
            }
            s_qx[col][t] = (unsigned short)idx;

            __syncwarp();
            if (tl == 0) {
                __threadfence_block();
                prog[col] = chunk + 1;
            }
        }
        return;
    }

    // ================= RECURRENCE ROLE (warps 7-13) =========
    const int rtid = tid - COLS_PB * 16;
    const int j  = rtid & 15;
    const int gb = rtid >> 4;                     // 0..13
    const int breal = blockIdx.x * COLS_PB + gb;
    const bool valid = (breal < B_DIM);
    const int b  = valid ? breal : (B_DIM - 1);   // clamp tail
    const unsigned gmask = (rtid & 16) ? 0xFFFF0000u : 0x0000FFFFu;

    float w0r[16], w1r[16], w2r[16];
    #pragma unroll
    for (int k = 0; k < 16; k++) {
        w0r[k] = m2q_w0[j * 16 + k];
        w1r[k] = m2q_w1[j * 16 + k];
        w2r[k] = m2q_w2[(j & 7) * 16 + k];
    }
    const float b0r = m2q_b0[j];
    const float b1r = m2q_b1[j];
    const float b2r = m2q_b2[j & 7];

    int p3 = 1;
    #pragma unroll
    for (int i = 0; i < 8; i++) if (i < (j & 7)) p3 *= 3;

    while (prog[gb] < 1) __nanosleep(64);
    __threadfence_block();
    int xq = (int)s_qx[gb][0];
    float4 gi = __ldg(&g_GI4[xq * 16 + j]);
    int qp = NQ;

    for (int t = 0; t < T_DIM; t++) {
        // 2-way bucket probe (overlaps the ghm load)
        const unsigned key = (unsigned)qp * 6561u + (unsigned)xq;
        const unsigned tag = key + 1u;
        const unsigned bkt = (key * 2654435761u) & MEMO_BKT_MASK;
        ulonglong2 e = *reinterpret_cast<const ulonglong2*>(&g_memo[bkt * 2]);

        float4 ghm = __ldg(&g_GHM[qp * 16 + j]);   // critical load (miss path)

        float4 gin = gi;
        int xqn = xq;
        if (t + 1 < T_DIM) {
            const int tn = t + 1;
            if ((tn & 15) == 0) {
                const int need = (tn >> 4) + 1;
                if (prog[gb] < need) {
                    while (prog[gb] < need) __nanosleep(64);
                }
                __threadfence_block();
            }
            xqn = (int)s_qx[gb][tn];
            gin = __ldg(&g_GI4[xqn * 16 + j]);
        }

        bool hit0 = ((unsigned)(e.x >> 32) == tag);
        bool hit1 = ((unsigned)(e.y >> 32) == tag);
        int qn;
        if (__all_sync(0xffffffffu, hit0 | hit1)) {   // warp-wide decision
            qn = (int)(unsigned)((hit0 ? e.x : e.y) & 0xffffffffu);
        } else {
            float r  = sigf(gi.x + ghm.x);
            float z  = sigf(gi.y + ghm.y);
            float n  = tanhf(gi.z + r * ghm.z);
            float ht = (1.0f - z) * n + z * ghm.w;

            s_ht[gb][j] = ht;
            __syncwarp();

            float a0a = 0.0f, a0b = 0.0f;
            #pragma unroll
            for (int k4 = 0; k4 < 4; k4 += 2) {
                float4 v0 = reinterpret_cast<const float4*>(s_ht[gb])[k4];
                float4 v1 = reinterpret_cast<const float4*>(s_ht[gb])[k4 + 1];
                a0a += w0r[4 * k4 + 0] * v0.x; a0a += w0r[4 * k4 + 1] * v0.y;
                a0a += w0r[4 * k4 + 2] * v0.z; a0a += w0r[4 * k4 + 3] * v0.w;
                a0b += w0r[4 * k4 + 4] * v1.x; a0b += w0r[4 * k4 + 5] * v1.y;
                a0b += w0r[4 * k4 + 6] * v1.z; a0b += w0r[4 * k4 + 7] * v1.w;
            }
            float q1 = tanhf((a0a + a0b) + b0r);
            s_q1[gb][j] = q1;
            __syncwarp();

            float a1a = 0.0f, a1b = 0.0f;
            #pragma unroll
            for (int k4 = 0; k4 < 4; k4 += 2) {
                float4 v0 = reinterpret_cast<const float4*>(s_q1[gb])[k4];
                float4 v1 = reinterpret_cast<const float4*>(s_q1[gb])[k4 + 1];
                a1a += w1r[4 * k4 + 0] * v0.x; a1a += w1r[4 * k4 + 1] * v0.y;
                a1a += w1r[4 * k4 + 2] * v0.z; a1a += w1r[4 * k4 + 3] * v0.w;
                a1b += w1r[4 * k4 + 4] * v1.x; a1b += w1r[4 * k4 + 5] * v1.y;
                a1b += w1r[4 * k4 + 6] * v1.z; a1b += w1r[4 * k4 + 7] * v1.w;
            }
            float q2v = tanhf((a1a + a1b) + b1r);
            s_q2[gb][j] = q2v;
            __syncwarp();

            float a2a = 0.0f, a2b = 0.0f;
            #pragma unroll
            for (int k4 = 0; k4 < 4; k4 += 2) {
                float4 v0 = reinterpret_cast<const float4*>(s_q2[gb])[k4];
                float4 v1 = reinterpret_cast<const float4*>(s_q2[gb])[k4 + 1];
                a2a += w2r[4 * k4 + 0] * v0.x; a2a += w2r[4 * k4 + 1] * v0.y;
                a2a += w2r[4 * k4 + 2] * v0.z; a2a += w2r[4 * k4 + 3] * v0.w;
                a2b += w2r[4 * k4 + 4] * v1.x; a2b += w2r[4 * k4 + 5] * v1.y;
                a2b += w2r[4 * k4 + 6] * v1.z; a2b += w2r[4 * k4 + 7] * v1.w;
            }
            float v = (a2a + a2b) + b2r;

            int d = (v > thr) - (v < -thr);
            int s = __reduce_add_sync(gmask, d * p3);   // 16-lane sum = 2*code
            qn = 3280 + (s >> 1);

            if ((rtid & 15) == 0) {
                unsigned long long ent =
                    (((unsigned long long)tag) << 32) | (unsigned)qn;
                unsigned t0 = (unsigned)(e.x >> 32);
                int slot = (t0 == 0u || t0 == tag) ? 0 : 1;
                g_memo[bkt * 2 + slot] = ent;
            }
        }

        if (valid)
            out[((size_t)(t * B_DIM + b)) * 16 + j] = __ldg(&g_OUT[qn * 16 + j]);
        qp = qn;
        gi = gin;
        xq = xqn;
    }
}

// ---------------------------------------------------------------------------
extern "C" void kernel_launch(void* const* d_in, const int* in_sizes, int n_in,
                              void* d_out, int out_size)
{
    (void)in_sizes; (void)n_in; (void)out_size;
    const float* x       = (const float*)d_in[0];
    const float* obs_w0  = (const float*)d_in[1];
    const float* obs_b0  = (const float*)d_in[2];
    const float* obs_w1  = (const float*)d_in[3];
    const float* obs_b1  = (const float*)d_in[4];
    const float* obs_w2  = (const float*)d_in[5];
    const float* obs_b2  = (const float*)d_in[6];
    const float* gru_wih = (const float*)d_in[7];
    const float* gru_whh = (const float*)d_in[8];
    const float* gru_bih = (const float*)d_in[9];
    const float* gru_bhh = (const float*)d_in[10];
    const float* m2q_w0  = (const float*)d_in[11];
    const float* m2q_b0  = (const float*)d_in[12];
    const float* m2q_w1  = (const float*)d_in[13];
    const float* m2q_b1  = (const float*)d_in[14];
    const float* m2q_w2  = (const float*)d_in[15];
    const float* m2q_b2  = (const float*)d_in[16];
    const float* q2m_w0  = (const float*)d_in[17];
    const float* q2m_b0  = (const float*)d_in[18];
    const float* q2m_w1  = (const float*)d_in[19];
    const float* q2m_b1  = (const float*)d_in[20];
    const float* q2m_w2  = (const float*)d_in[21];
    const float* q2m_b2  = (const float*)d_in[22];
    const float* act_w   = (const float*)d_in[23];
    const float* act_b   = (const float*)d_in[24];
    float* out = (float*)d_out;

    memo_clear<<<MEMO_BKTS / 256, 256>>>();   // per-launch: identical work every call
    setup_all<<<(NQ + 1 + 15) / 16, 256>>>(
        q2m_w0, q2m_b0, q2m_w1, q2m_b1, q2m_w2, q2m_b2,
        act_w, act_b, gru_wih, gru_whh, gru_bih, gru_bhh);
    fused_kernel<<<NBLK, THREADS>>>(
        out, x, obs_w0, obs_b0, obs_w1, obs_b1, obs_w2, obs_b2,
        m2q_w0, m2q_b0, m2q_w1, m2q_b1, m2q_w2, m2q_b2);
}